// round 2
// baseline (speedup 1.0000x reference)
#include <cuda_runtime.h>

// MatrixMemory split into two pure-direction streaming kernels:
//   Kernel A: y = state @ query   (512 MB pure READ stream + 2 MB y writes)
//   Kernel B: dM = d_out outer k  (512 MB pure WRITE stream + 6 MB vector reads)
// Rationale: avoid fine-grained HBM read/write direction mixing (bus turnaround).

#define B_  2048
#define DK_ 256
#define DV_ 256

// ---------------- Kernel A: batched GEMV (pure read) ----------------
// Block = 256 threads = 8 warps, covers 32 consecutive rows of one batch.
// Each warp handles 4 rows -> 8 front-batched LDG.128 per thread (deep MLP).
__global__ __launch_bounds__(256, 8)
void y_kernel(const float4* __restrict__ state,   // [B, DV, DK] as float4
              const float*  __restrict__ query,   // [B, DK]
              float*        __restrict__ y)       // [B, DV]
{
    const int b  = blockIdx.x >> 3;            // 8 blocks per batch
    const int rb = (blockIdx.x & 7) << 5;      // 32 rows per block

    __shared__ float4 sq[64];
    const int tid = threadIdx.x;
    if (tid < 64)
        sq[tid] = reinterpret_cast<const float4*>(query + (long)b * DK_)[tid];
    __syncthreads();

    const int w    = tid >> 5;
    const int lane = tid & 31;
    const long row0 = (long)b * DV_ + rb + w * 4;   // first of 4 rows for this warp
    const float4* p = state + row0 * (DK_ / 4);

    // front-batch 8 independent 16B loads (4 rows x 2)
    float4 a[8];
    #pragma unroll
    for (int j = 0; j < 4; j++) {
        a[2*j]   = __ldcs(p + j * 64 + lane);
        a[2*j+1] = __ldcs(p + j * 64 + 32 + lane);
    }

    const float4 q0 = sq[lane];
    const float4 q1 = sq[lane + 32];

    #pragma unroll
    for (int j = 0; j < 4; j++) {
        float s = a[2*j].x   * q0.x + a[2*j].y   * q0.y
                + a[2*j].z   * q0.z + a[2*j].w   * q0.w
                + a[2*j+1].x * q1.x + a[2*j+1].y * q1.y
                + a[2*j+1].z * q1.z + a[2*j+1].w * q1.w;
        #pragma unroll
        for (int off = 16; off > 0; off >>= 1)
            s += __shfl_xor_sync(0xFFFFFFFFu, s, off);
        if (lane == 0) y[row0 + j] = s;
    }
}

// ---------------- Kernel B: batched outer product (pure write) ----------------
__global__ __launch_bounds__(256, 8)
void dm_kernel(const float*  __restrict__ keyv,   // [B, DK]
               const float*  __restrict__ dout,   // [B, DV]
               float4*       __restrict__ dM)     // [B, DV, DK] as float4
{
    const int b  = blockIdx.x >> 3;
    const int rb = (blockIdx.x & 7) << 5;

    __shared__ float4 sk[64];
    const int tid = threadIdx.x;
    if (tid < 64)
        sk[tid] = reinterpret_cast<const float4*>(keyv + (long)b * DK_)[tid];
    __syncthreads();

    const int w    = tid >> 5;
    const int lane = tid & 31;
    const long row0 = (long)b * DV_ + rb + w * 4;

    const float d0 = __ldg(dout + row0);
    const float d1 = __ldg(dout + row0 + 1);
    const float d2 = __ldg(dout + row0 + 2);
    const float d3 = __ldg(dout + row0 + 3);
    const float dv[4] = {d0, d1, d2, d3};

    const float4 k0 = sk[lane];
    const float4 k1 = sk[lane + 32];

    float4* p = dM + row0 * (DK_ / 4);
    #pragma unroll
    for (int j = 0; j < 4; j++) {
        const float d = dv[j];
        float4 o0 = make_float4(d * k0.x, d * k0.y, d * k0.z, d * k0.w);
        float4 o1 = make_float4(d * k1.x, d * k1.y, d * k1.z, d * k1.w);
        __stcs(p + j * 64 + lane,      o0);
        __stcs(p + j * 64 + 32 + lane, o1);
    }
}

extern "C" void kernel_launch(void* const* d_in, const int* in_sizes, int n_in,
                              void* d_out, int out_size)
{
    const float4* state = (const float4*)d_in[0];
    const float*  query = (const float*) d_in[1];
    const float*  keyv  = (const float*) d_in[2];
    const float*  dov   = (const float*) d_in[3];

    float* out = (float*)d_out;
    float*  y  = out;                              // [B, DV]
    float4* dM = (float4*)(out + (long)B_ * DV_);  // [B, DV, DK]

    dim3 grid(B_ * 8);   // 8 blocks/batch, 8 warps, 4 rows/warp -> 32 rows/block
    dim3 block(256);
    y_kernel <<<grid, block>>>(state, query, y);
    dm_kernel<<<grid, block>>>(keyv, dov, dM);
}

// round 3
// speedup vs baseline: 1.0484x; 1.0484x over previous
#include <cuda_runtime.h>

// MatrixMemory fused single-pass (R3): y = state @ query, dM = d_out ⊗ key.
// vs R1: 4 rows/warp (8 front-batched LDG.128 + 8 STG.128 per thread) for
// deeper MLP and 4x fewer blocks; y staged in smem and written coalesced.

#define B_  2048
#define DK_ 256
#define DV_ 256

__global__ __launch_bounds__(256, 8)
void mm_fused3_kernel(const float4* __restrict__ state,   // [B, DV, DK] as float4
                      const float*  __restrict__ query,   // [B, DK]
                      const float*  __restrict__ keyv,    // [B, DK]
                      const float*  __restrict__ dout,    // [B, DV]
                      float*        __restrict__ y,       // [B, DV]
                      float4*       __restrict__ dM)      // [B, DV, DK] as float4
{
    const int b  = blockIdx.x >> 3;            // 8 blocks per batch
    const int rb = (blockIdx.x & 7) << 5;      // 32 v-rows per block

    __shared__ float4 sq[64];   // query[b]
    __shared__ float4 sk[64];   // key[b]
    __shared__ float  sy[32];   // y staging for this block's 32 rows

    const int tid = threadIdx.x;
    if (tid < 64) {
        sq[tid] = reinterpret_cast<const float4*>(query + (long)b * DK_)[tid];
    } else if (tid < 128) {
        sk[tid - 64] = reinterpret_cast<const float4*>(keyv + (long)b * DK_)[tid - 64];
    }
    __syncthreads();

    const int w    = tid >> 5;
    const int lane = tid & 31;
    const long row0 = (long)b * DV_ + rb + w * 4;   // 4 rows per warp
    const float4* p = state + row0 * (DK_ / 4);

    // ---- front-batch 8 independent streaming loads (4 rows x 2 x 16B) ----
    float4 a[8];
    #pragma unroll
    for (int j = 0; j < 4; j++) {
        a[2*j]   = __ldcs(p + j * 64 + lane);
        a[2*j+1] = __ldcs(p + j * 64 + 32 + lane);
    }

    // d_out scalars for the 4 rows (tiny, cached)
    float dv[4];
    #pragma unroll
    for (int j = 0; j < 4; j++) dv[j] = __ldg(dout + row0 + j);

    const float4 q0 = sq[lane];
    const float4 q1 = sq[lane + 32];
    const float4 k0 = sk[lane];
    const float4 k1 = sk[lane + 32];

    float4* pd = dM + row0 * (DK_ / 4);

    #pragma unroll
    for (int j = 0; j < 4; j++) {
        // dot-product partial + warp reduce
        float s = a[2*j].x   * q0.x + a[2*j].y   * q0.y
                + a[2*j].z   * q0.z + a[2*j].w   * q0.w
                + a[2*j+1].x * q1.x + a[2*j+1].y * q1.y
                + a[2*j+1].z * q1.z + a[2*j+1].w * q1.w;
        #pragma unroll
        for (int off = 16; off > 0; off >>= 1)
            s += __shfl_xor_sync(0xFFFFFFFFu, s, off);
        if (lane == 0) sy[w * 4 + j] = s;

        // outer-product row write (streaming)
        const float d = dv[j];
        float4 o0 = make_float4(d * k0.x, d * k0.y, d * k0.z, d * k0.w);
        float4 o1 = make_float4(d * k1.x, d * k1.y, d * k1.z, d * k1.w);
        __stcs(pd + j * 64 + lane,      o0);
        __stcs(pd + j * 64 + 32 + lane, o1);
    }

    // ---- coalesced y writeback: 32 floats = 8 x STG.128 ----
    __syncthreads();
    if (tid < 8) {
        reinterpret_cast<float4*>(y + (long)b * DV_ + rb)[tid] =
            reinterpret_cast<const float4*>(sy)[tid];
    }
}

extern "C" void kernel_launch(void* const* d_in, const int* in_sizes, int n_in,
                              void* d_out, int out_size)
{
    const float4* state = (const float4*)d_in[0];
    const float*  query = (const float*) d_in[1];
    const float*  keyv  = (const float*) d_in[2];
    const float*  dov   = (const float*) d_in[3];

    float* out = (float*)d_out;
    float*  y  = out;                              // [B, DV]
    float4* dM = (float4*)(out + (long)B_ * DV_);  // [B, DV, DK]

    dim3 grid(B_ * 8);   // 8 blocks/batch, 8 warps, 4 rows/warp
    dim3 block(256);
    mm_fused3_kernel<<<grid, block>>>(state, query, keyv, dov, y, dM);
}